// round 3
// baseline (speedup 1.0000x reference)
#include <cuda_runtime.h>

// Permutation: out[b,i,j,W,p,q] = x[b, 2i+p, 2j+q, W]   (k=2 unfold repack)
// x: (16, 64, 224, 224) fp32 -> pure streaming permutation, HBM-bound.
//
// R3 changes vs R2:
//  * XOR-swizzled smem (g(f) = f ^ ((f>>3)&7) in float4 units): the R2 STS
//    pattern (f = 4*tid+m, 64B lane stride) was a 16-way bank conflict; the
//    swizzle is conflict-free for BOTH the stride-4 STS and stride-1 LDS.
//  * Persistent grid-stride loop (148 SMs x 9 resident blocks) instead of
//    14336 one-shot blocks: removes ~10 wave transitions.

#define H 224
#define W_DIM 224
#define C 64
#define JN 112          // h/2
#define IN 32           // c/2
#define W4 56           // W_DIM/4 float4 per row
#define THREADS 224     // 4 segments x 56 groups
#define NSEG 57344      // 16 * 32 * 112
#define GRID 1332       // 148 * 9 resident

__device__ __forceinline__ int sw(int f) { return f ^ ((f >> 3) & 7); }

__global__ void __launch_bounds__(THREADS) KernelActivation_perm3(
    const float4* __restrict__ x4, float4* __restrict__ out4)
{
    __shared__ float4 s[4 * W_DIM];     // 14336 B

    const int tid = threadIdx.x;
    const int sl  = tid / W4;           // 0..3 local segment
    const int wg  = tid % W4;           // 0..55 float4 group in row

    for (int seg4 = blockIdx.x * 4; seg4 < NSEG; seg4 += GRID * 4) {
        const int seg = seg4 + sl;
        const int j = seg % JN;
        const int t = seg / JN;
        const int i = t & (IN - 1);
        const int b = t >> 5;

        // x[b, 2i+p, 2j+q, :] rows (in float4 units)
        const int base = ((b * C + 2 * i) * H + 2 * j) * W4 + wg;

        const float4 r00 = __ldcs(&x4[base]);                 // p=0 q=0
        const float4 r01 = __ldcs(&x4[base + W4]);            // p=0 q=1
        const float4 r10 = __ldcs(&x4[base + H * W4]);        // p=1 q=0
        const float4 r11 = __ldcs(&x4[base + H * W4 + W4]);   // p=1 q=1

        __syncthreads();  // previous iteration's drain must finish

        // STS: f = 4*tid + m, swizzled (conflict-free)
        const int f0 = 4 * tid;
        s[sw(f0 + 0)] = make_float4(r00.x, r01.x, r10.x, r11.x);
        s[sw(f0 + 1)] = make_float4(r00.y, r01.y, r10.y, r11.y);
        s[sw(f0 + 2)] = make_float4(r00.z, r01.z, r10.z, r11.z);
        s[sw(f0 + 3)] = make_float4(r00.w, r01.w, r10.w, r11.w);

        __syncthreads();

        // drain: contiguous 14336B block store, LDS swizzled (conflict-free)
        float4* dst = &out4[(long)seg4 * W_DIM];
#pragma unroll
        for (int m = 0; m < 4; m++) {
            const int f = m * THREADS + tid;
            __stcs(&dst[f], s[sw(f)]);
        }
    }
}

extern "C" void kernel_launch(void* const* d_in, const int* in_sizes, int n_in,
                              void* d_out, int out_size)
{
    const float4* x4 = (const float4*)d_in[0];
    float4* out4 = (float4*)d_out;
    KernelActivation_perm3<<<GRID, THREADS>>>(x4, out4);
}

// round 4
// speedup vs baseline: 1.0259x; 1.0259x over previous
#include <cuda_runtime.h>

// Permutation: out[b,i,j,W,p,q] = x[b, 2i+p, 2j+q, W]   (k=2 unfold repack)
// x: (16, 64, 224, 224) fp32 -> pure streaming permutation, HBM-bound.
//
// R4 = R2 (one-shot grid, good occupancy, self-balancing waves)
//    + R3's XOR-swizzled smem (conflict-free for both the stride-4 STS
//      interleave and the stride-1 LDS drain).
// R3's persistent grid is dropped: at 44 regs only 6 blocks/SM were
// resident, so GRID=1332 ran as 888 + ragged 444 -> half-idle tail.

#define H 224
#define W_DIM 224
#define C 64
#define JN 112          // h/2
#define IN 32           // c/2
#define W4 56           // W_DIM/4 float4 per row
#define THREADS 224     // 4 segments x 56 groups
#define GRID 14336      // 57344 segments / 4

__device__ __forceinline__ int sw(int f) { return f ^ ((f >> 3) & 7); }

__global__ void __launch_bounds__(THREADS) KernelActivation_perm4(
    const float4* __restrict__ x4, float4* __restrict__ out4)
{
    __shared__ float4 s[4 * W_DIM];     // 14336 B

    const int tid  = threadIdx.x;
    const int sl   = tid / W4;          // 0..3 local segment
    const int wg   = tid % W4;          // 0..55 float4 group in row
    const int seg4 = blockIdx.x * 4;
    const int seg  = seg4 + sl;

    const int j = seg % JN;
    const int t = seg / JN;
    const int i = t & (IN - 1);
    const int b = t >> 5;

    // x[b, 2i+p, 2j+q, :] rows (float4 units)
    const int base = ((b * C + 2 * i) * H + 2 * j) * W4 + wg;

    const float4 r00 = __ldcs(&x4[base]);                 // p=0 q=0
    const float4 r01 = __ldcs(&x4[base + W4]);            // p=0 q=1
    const float4 r10 = __ldcs(&x4[base + H * W4]);        // p=1 q=0
    const float4 r11 = __ldcs(&x4[base + H * W4 + W4]);   // p=1 q=1

    // STS: f = 4*tid + m, swizzled -> conflict-free
    const int f0 = 4 * tid;
    s[sw(f0 + 0)] = make_float4(r00.x, r01.x, r10.x, r11.x);
    s[sw(f0 + 1)] = make_float4(r00.y, r01.y, r10.y, r11.y);
    s[sw(f0 + 2)] = make_float4(r00.z, r01.z, r10.z, r11.z);
    s[sw(f0 + 3)] = make_float4(r00.w, r01.w, r10.w, r11.w);

    __syncthreads();

    // drain: contiguous 14336B block store, LDS swizzled -> conflict-free
    float4* dst = &out4[(long)seg4 * W_DIM];
#pragma unroll
    for (int m = 0; m < 4; m++) {
        const int f = m * THREADS + tid;
        __stcs(&dst[f], s[sw(f)]);
    }
}

extern "C" void kernel_launch(void* const* d_in, const int* in_sizes, int n_in,
                              void* d_out, int out_size)
{
    const float4* x4 = (const float4*)d_in[0];
    float4* out4 = (float4*)d_out;
    KernelActivation_perm4<<<GRID, THREADS>>>(x4, out4);
}

// round 5
// speedup vs baseline: 1.0300x; 1.0040x over previous
#include <cuda_runtime.h>
#include <cstdint>

// Permutation: out[b,i,j,W,p,q] = x[b, 2i+p, 2j+q, W]   (k=2 unfold repack)
// x: (16, 64, 224, 224) fp32 -> pure streaming permutation, HBM-bound.
//
// R5: TMA bulk ends. Per block (4 segments, fixed (b,i), j=j0..j0+3):
//   in : 2x cp.async.bulk G->S of 7168B   (rows c=2i and c=2i+1, h=2j0..2j0+7)
//   mid: 16 scalar LDS (stride-4B, conflict-free) + 4 STS.128 contiguous
//   out: 1x cp.async.bulk S->G of 14336B  (contiguous output block)
// Long sequential bursts -> better DRAM page locality than 128B LDG/STG soup.

#define W_DIM 224
#define THREADS 224
#define GRID 14336          // 57344 segments / 4

__device__ __forceinline__ uint32_t smem_u32(const void* p) {
    return (uint32_t)__cvta_generic_to_shared(p);
}

__global__ void __launch_bounds__(THREADS) KernelActivation_perm5(
    const float* __restrict__ x, float4* __restrict__ out)
{
    __shared__ __align__(16) float  sin_[16 * W_DIM];  // A[8][224] then B[8][224]
    __shared__ __align__(16) float4 sout[4 * W_DIM];   // 14336 B
    __shared__ uint64_t mbar;

    const int tid = threadIdx.x;
    const int blk = blockIdx.x;
    const int j0  = 4 * (blk % 28);     // 28 j-groups per (b,i)
    const int t   = blk / 28;
    const int i   = t & 31;
    const int b   = t >> 5;

    // x[b, 2i, 2j0, 0] : 8 h-rows x 224 floats contiguous = 7168B
    const float* srcA = x + (((b * 64 + 2 * i) * 224) + 2 * j0) * 224;
    const uint32_t mb = smem_u32(&mbar);

    if (tid == 0) {
        asm volatile("mbarrier.init.shared.b64 [%0], 1;" :: "r"(mb) : "memory");
    }
    __syncthreads();

    if (tid == 0) {
        asm volatile("mbarrier.arrive.expect_tx.shared.b64 _, [%0], %1;"
                     :: "r"(mb), "r"(14336u) : "memory");
        const uint32_t s0 = smem_u32(sin_);
        asm volatile(
            "cp.async.bulk.shared::cta.global.mbarrier::complete_tx::bytes [%0], [%1], %2, [%3];"
            :: "r"(s0), "l"(srcA), "r"(7168u), "r"(mb) : "memory");
        asm volatile(
            "cp.async.bulk.shared::cta.global.mbarrier::complete_tx::bytes [%0], [%1], %2, [%3];"
            :: "r"(s0 + 7168u), "l"(srcA + 224 * 224), "r"(7168u), "r"(mb) : "memory");
    }

    // all threads wait for both loads (phase 0)
    {
        uint32_t done;
        asm volatile(
            "{\n\t.reg .pred p;\n\t"
            "mbarrier.try_wait.parity.shared.b64 p, [%1], 0;\n\t"
            "selp.b32 %0, 1, 0, p;\n\t}"
            : "=r"(done) : "r"(mb) : "memory");
        while (!done) {
            asm volatile(
                "{\n\t.reg .pred p;\n\t"
                "mbarrier.try_wait.parity.shared.b64 p, [%1], 0, 0x989680;\n\t"
                "selp.b32 %0, 1, 0, p;\n\t}"
                : "=r"(done) : "r"(mb) : "memory");
        }
    }

    // interleave: segment m (j=j0+m), wout = tid
    //   out4 = { A[2m][w], A[2m+1][w], B[2m][w], B[2m+1][w] }
#pragma unroll
    for (int m = 0; m < 4; m++) {
        const float* A = sin_ + 2 * m * W_DIM;
        float4 v;
        v.x = A[tid];                       // p=0 q=0
        v.y = A[W_DIM + tid];               // p=0 q=1
        v.z = A[8 * W_DIM + tid];           // p=1 q=0
        v.w = A[9 * W_DIM + tid];           // p=1 q=1
        sout[m * W_DIM + tid] = v;
    }

    // make generic STS visible to the async proxy, then bulk store
    asm volatile("fence.proxy.async.shared::cta;" ::: "memory");
    __syncthreads();

    if (tid == 0) {
        char* dst = (char*)out + (size_t)blk * 14336;
        asm volatile(
            "cp.async.bulk.global.shared::cta.bulk_group [%0], [%1], %2;"
            :: "l"(dst), "r"(smem_u32(sout)), "r"(14336u) : "memory");
        asm volatile("cp.async.bulk.commit_group;" ::: "memory");
        asm volatile("cp.async.bulk.wait_group 0;" ::: "memory");
    }
}

extern "C" void kernel_launch(void* const* d_in, const int* in_sizes, int n_in,
                              void* d_out, int out_size)
{
    const float* x = (const float*)d_in[0];
    float4* out = (float4*)d_out;
    KernelActivation_perm5<<<GRID, THREADS>>>(x, out);
}